// round 1
// baseline (speedup 1.0000x reference)
#include <cuda_runtime.h>
#include <math.h>

#define Bn 16
#define Cn 32
#define Sn 256
#define Mn 12
#define Rn 24
#define Ln 4
#define BCn (Bn*Cn)

// ---- scratch (device globals: no allocation allowed) ----
__device__ float g_h0[BCn*Sn*Sn];       // 134 MB ping
__device__ float g_h1[BCn*Sn*Sn];       // 134 MB pong
__device__ float g_Yr[BCn*Sn*Mn];       // stage A out  [bc][h][k]
__device__ float g_Yi[BCn*Sn*Mn];
__device__ float g_Zr[BCn*Rn*Mn];       // stage B out  [bc][r][k]
__device__ float g_Zi[BCn*Rn*Mn];
__device__ float g_Or[BCn*Rn*Mn];       // mixed modes  [bc][r][k]
__device__ float g_Oi[BCn*Rn*Mn];
__device__ float g_Tr[BCn*Mn*Sn];       // inverse-H out [bc][k][h]
__device__ float g_Ti[BCn*Mn*Sn];
__device__ float g_cw[Mn*Sn];           // cos(2pi k w/256)
__device__ float g_sw[Mn*Sn];
__device__ float g_ch[Rn*Sn];           // cos(2pi ky h/256), ky in {0..11, 244..255}
__device__ float g_sh[Rn*Sn];

__global__ void k_setup() {
    int w = threadIdx.x;                 // 0..255
    const double c = 2.0 * M_PI / 256.0;
    for (int k = 0; k < Mn; k++) {
        int t = (k * w) & 255;
        double a = c * (double)t;
        g_cw[k*Sn + w] = (float)cos(a);
        g_sw[k*Sn + w] = (float)sin(a);
    }
    for (int r = 0; r < Rn; r++) {
        int ky = (r < Mn) ? r : (Sn - Mn + (r - Mn));
        int t = (ky * w) & 255;
        double a = c * (double)t;
        g_ch[r*Sn + w] = (float)cos(a);
        g_sh[r*Sn + w] = (float)sin(a);
    }
}

// lifting: h0[b,c,y,w] = pw[c,0]*x + pw[c,1]*gy + pw[c,2]*gx + pb[c]
__global__ void k_lift(const float* __restrict__ x,
                       const float* __restrict__ pw,
                       const float* __restrict__ pb) {
    int by = blockIdx.x;                 // b*S + y
    int b = by >> 8, y = by & 255;
    int w = threadIdx.x;
    float xin = x[(size_t)by*Sn + w];
    float gy = -1.f + (2.f/255.f) * (float)y;
    float gx = -1.f + (2.f/255.f) * (float)w;
    #pragma unroll 4
    for (int c = 0; c < Cn; c++) {
        float v = pw[c*3+0]*xin + pw[c*3+1]*gy + pw[c*3+2]*gx + pb[c];
        g_h0[(((size_t)(b*Cn + c))*Sn + y)*Sn + w] = v;
    }
}

// stage A: Y[bc,h,k] = sum_w h[bc,h,w] * e^{-2pi i k w/256}, k=0..11
// block: 128 thr, 16 rows; thread = (row, 3 consecutive q of 24 [12 re | 12 im])
__global__ void k_stageA(int sel) {
    const float* h = sel ? g_h1 : g_h0;
    int blk = blockIdx.x;
    int bc = blk >> 4;
    int rb = (blk & 15) * 16;
    __shared__ float4 s_x[16][65];       // padded: conflict-free across rows
    __shared__ float4 s_t[24][64];       // [q][w4], q<12: cos, q>=12: sin
    const float4* hrow = (const float4*)(h + ((size_t)bc*Sn + rb)*Sn);
    for (int i = threadIdx.x; i < 16*64; i += 128)
        s_x[i >> 6][i & 63] = hrow[i];
    for (int i = threadIdx.x; i < 24*64; i += 128) {
        int q = i >> 6, cc = i & 63;
        const float* tab = (q < Mn) ? (g_cw + q*Sn) : (g_sw + (q - Mn)*Sn);
        s_t[q][cc] = ((const float4*)tab)[cc];
    }
    __syncthreads();
    int row = threadIdx.x >> 3;
    int q0  = (threadIdx.x & 7) * 3;
    float a0 = 0.f, a1 = 0.f, a2 = 0.f;
    #pragma unroll 16
    for (int w4 = 0; w4 < 64; w4++) {
        float4 xv = s_x[row][w4];
        float4 t0 = s_t[q0+0][w4];
        float4 t1 = s_t[q0+1][w4];
        float4 t2 = s_t[q0+2][w4];
        a0 += xv.x*t0.x + xv.y*t0.y + xv.z*t0.z + xv.w*t0.w;
        a1 += xv.x*t1.x + xv.y*t1.y + xv.z*t1.z + xv.w*t1.w;
        a2 += xv.x*t2.x + xv.y*t2.y + xv.z*t2.z + xv.w*t2.w;
    }
    int hg = rb + row;
    size_t base = ((size_t)bc*Sn + hg)*Mn;
    float av[3] = {a0, a1, a2};
    #pragma unroll
    for (int j = 0; j < 3; j++) {
        int q = q0 + j;
        if (q < Mn) g_Yr[base + q]       =  av[j];
        else        g_Yi[base + q - Mn]  = -av[j];   // Yi = -sum x*sin
    }
}

// stage B: Z[bc,r,k] = sum_h Y[bc,h,k] * e^{-2pi i ky(r) h/256}
__global__ void k_stageB() {
    int bc = blockIdx.x;
    __shared__ float sYr[Sn*Mn];
    __shared__ float sYi[Sn*Mn];
    for (int i = threadIdx.x; i < Sn*Mn; i += 192) {
        sYr[i] = g_Yr[(size_t)bc*Sn*Mn + i];
        sYi[i] = g_Yi[(size_t)bc*Sn*Mn + i];
    }
    __syncthreads();
    int tid = threadIdx.x;               // 0..191
    int r = tid >> 3;                    // 0..23
    int m = tid & 7;
    int comp = m >> 2;                   // 0: real, 1: imag
    int k0 = (m & 3) * 3;                // 0,3,6,9
    float a0 = 0.f, a1 = 0.f, a2 = 0.f;
    const float* chp = g_ch + r*Sn;
    const float* shp = g_sh + r*Sn;
    for (int hh = 0; hh < Sn; hh++) {
        float cv = chp[hh], sv = shp[hh];
        int o = hh*Mn + k0;
        if (comp == 0) {
            a0 += sYr[o+0]*cv + sYi[o+0]*sv;
            a1 += sYr[o+1]*cv + sYi[o+1]*sv;
            a2 += sYr[o+2]*cv + sYi[o+2]*sv;
        } else {
            a0 += sYi[o+0]*cv - sYr[o+0]*sv;
            a1 += sYi[o+1]*cv - sYr[o+1]*sv;
            a2 += sYi[o+2]*cv - sYr[o+2]*sv;
        }
    }
    size_t ob = (size_t)bc*Rn*Mn + r*Mn + k0;
    if (comp == 0) { g_Zr[ob] = a0; g_Zr[ob+1] = a1; g_Zr[ob+2] = a2; }
    else           { g_Zi[ob] = a0; g_Zi[ob+1] = a1; g_Zi[ob+2] = a2; }
}

// mix: O[b,o,r,k] = (1/65536) * sum_i Z[b,i,r,k] * W[i,o,r',k]   (complex)
__global__ void k_mix(const float* __restrict__ w1r, const float* __restrict__ w1i,
                      const float* __restrict__ w2r, const float* __restrict__ w2i,
                      int l) {
    int rk = blockIdx.x;                 // 0..287
    int r = rk / Mn, k = rk % Mn;
    const float *Wr, *Wi; int kyw;
    if (r < Mn) { Wr = w1r; Wi = w1i; kyw = r; }
    else        { Wr = w2r; Wi = w2i; kyw = r - Mn; }
    size_t wbase = (size_t)l*Cn*Cn*Mn*Mn + (size_t)kyw*Mn + k;
    __shared__ float s_wr[Cn*Cn];
    __shared__ float s_wi[Cn*Cn];
    for (int idx = threadIdx.x; idx < Cn*Cn; idx += 256) {   // idx = i*32+o
        s_wr[idx] = Wr[wbase + (size_t)idx*(Mn*Mn)];
        s_wi[idx] = Wi[wbase + (size_t)idx*(Mn*Mn)];
    }
    __syncthreads();
    int warp = threadIdx.x >> 5, lane = threadIdx.x & 31;
    const float scale = 1.0f / (float)(Sn*Sn);
    for (int b = warp; b < Bn; b += 8) {
        size_t zidx = ((size_t)(b*Cn + lane))*Rn*Mn + rk;
        float zr = g_Zr[zidx], zi = g_Zi[zidx];
        float ar = 0.f, ai = 0.f;
        #pragma unroll
        for (int i = 0; i < Cn; i++) {
            float xr = __shfl_sync(0xffffffffu, zr, i);
            float xi = __shfl_sync(0xffffffffu, zi, i);
            float wr = s_wr[i*Cn + lane], wi = s_wi[i*Cn + lane];
            ar += xr*wr - xi*wi;
            ai += xr*wi + xi*wr;
        }
        g_Or[zidx] = ar*scale;
        g_Oi[zidx] = ai*scale;
    }
}

// inverse-H: T[bo,k,h] = sum_r O[bo,r,k] * e^{+2pi i ky(r) h/256}
__global__ void k_stageBinv() {
    int bo = blockIdx.x;
    __shared__ float sOr[Rn*Mn];
    __shared__ float sOi[Rn*Mn];
    for (int i = threadIdx.x; i < Rn*Mn; i += 256) {
        sOr[i] = g_Or[(size_t)bo*Rn*Mn + i];
        sOi[i] = g_Oi[(size_t)bo*Rn*Mn + i];
    }
    __syncthreads();
    int hh = threadIdx.x;
    float cv[Rn], sv[Rn];
    #pragma unroll
    for (int r = 0; r < Rn; r++) { cv[r] = g_ch[r*Sn + hh]; sv[r] = g_sh[r*Sn + hh]; }
    #pragma unroll 4
    for (int k = 0; k < Mn; k++) {
        float tr = 0.f, ti = 0.f;
        #pragma unroll
        for (int r = 0; r < Rn; r++) {
            float Or = sOr[r*Mn + k], Oi = sOi[r*Mn + k];
            tr += Or*cv[r] - Oi*sv[r];
            ti += Or*sv[r] + Oi*cv[r];
        }
        size_t tb = ((size_t)bo*Mn + k)*Sn + hh;
        g_Tr[tb] = tr;
        g_Ti[tb] = ti;
    }
}

// fused: inverse-W reconstruction + pointwise conv + bias (+ReLU | +projection)
__global__ void k_final(int sel,
                        const float* __restrict__ wsw, const float* __restrict__ wsb,
                        const float* __restrict__ qw,  const float* __restrict__ qb,
                        int l, int do_relu, int do_proj, float* __restrict__ out) {
    const float* hc = sel ? g_h1 : g_h0;
    float* hn       = sel ? g_h0 : g_h1;
    int by = blockIdx.x;
    int b = by >> 8, y = by & 255;
    __shared__ float s_tr[Cn*Mn];
    __shared__ float s_ti[Cn*Mn];
    __shared__ float s_ws[Cn*Cn];
    __shared__ float s_wb[Cn];
    __shared__ float s_qw[Cn];
    for (int idx = threadIdx.x; idx < Cn*Mn; idx += 256) {
        int o = idx / Mn, k = idx % Mn;
        size_t tb = (((size_t)(b*Cn + o))*Mn + k)*Sn + y;
        s_tr[idx] = g_Tr[tb];
        s_ti[idx] = g_Ti[tb];
    }
    for (int idx = threadIdx.x; idx < Cn*Cn; idx += 256)
        s_ws[idx] = wsw[(size_t)l*Cn*Cn + idx];          // [o][i]
    if (threadIdx.x < Cn) {
        s_wb[threadIdx.x] = wsb[l*Cn + threadIdx.x];
        s_qw[threadIdx.x] = qw[threadIdx.x];
    }
    __syncthreads();
    int w = threadIdx.x;
    float cww[Mn], sww[Mn];
    #pragma unroll
    for (int k = 0; k < Mn; k++) { cww[k] = g_cw[k*Sn + w]; sww[k] = g_sw[k*Sn + w]; }
    float hin[Cn];
    size_t hbase = (((size_t)b*Cn)*Sn + y)*Sn + w;
    #pragma unroll
    for (int i = 0; i < Cn; i++) hin[i] = hc[hbase + (size_t)i*Sn*Sn];
    float proj = 0.f;
    #pragma unroll 4
    for (int o = 0; o < Cn; o++) {
        float acc = s_wb[o];
        #pragma unroll
        for (int i = 0; i < Cn; i++) acc += s_ws[o*Cn + i]*hin[i];
        float four = s_tr[o*Mn];                          // DC: imag ignored (C2R)
        #pragma unroll
        for (int k = 1; k < Mn; k++)
            four += 2.f*(s_tr[o*Mn + k]*cww[k] - s_ti[o*Mn + k]*sww[k]);
        float v = acc + four;
        if (do_relu) v = fmaxf(v, 0.f);
        if (do_proj) proj += s_qw[o]*v;
        else         hn[hbase + (size_t)o*Sn*Sn] = v;
    }
    if (do_proj) out[(size_t)by*Sn + w] = proj + qb[0];
}

extern "C" void kernel_launch(void* const* d_in, const int* in_sizes, int n_in,
                              void* d_out, int out_size) {
    (void)in_sizes; (void)n_in; (void)out_size;
    const float* x    = (const float*)d_in[0];
    const float* p_w  = (const float*)d_in[1];
    const float* p_b  = (const float*)d_in[2];
    const float* ws_w = (const float*)d_in[3];
    const float* ws_b = (const float*)d_in[4];
    const float* w1r  = (const float*)d_in[5];
    const float* w1i  = (const float*)d_in[6];
    const float* w2r  = (const float*)d_in[7];
    const float* w2i  = (const float*)d_in[8];
    const float* q_w  = (const float*)d_in[9];
    const float* q_b  = (const float*)d_in[10];
    float* out = (float*)d_out;

    k_setup<<<1, 256>>>();
    k_lift<<<Bn*Sn, 256>>>(x, p_w, p_b);
    int sel = 0;
    for (int l = 0; l < Ln; l++) {
        k_stageA  <<<BCn*16, 128>>>(sel);
        k_stageB  <<<BCn,    192>>>();
        k_mix     <<<Rn*Mn,  256>>>(w1r, w1i, w2r, w2i, l);
        k_stageBinv<<<BCn,   256>>>();
        k_final   <<<Bn*Sn,  256>>>(sel, ws_w, ws_b, q_w, q_b,
                                    l, (l < Ln-1) ? 1 : 0, (l == Ln-1) ? 1 : 0, out);
        sel ^= 1;
    }
}

// round 2
// speedup vs baseline: 1.0030x; 1.0030x over previous
#include <cuda_runtime.h>
#include <math.h>

#define Bn 16
#define Cn 32
#define Sn 256
#define Mn 12
#define Rn 24
#define Ln 4
#define BCn (Bn*Cn)

// ---- scratch (device globals: no allocation allowed) ----
__device__ float g_h0[BCn*Sn*Sn];       // 134 MB ping
__device__ float g_h1[BCn*Sn*Sn];       // 134 MB pong
__device__ float g_Yr[BCn*Sn*Mn];       // stage A out  [bc][h][k]
__device__ float g_Yi[BCn*Sn*Mn];
__device__ float g_Zr[BCn*Rn*Mn];       // stage B out  [bc][r][k]
__device__ float g_Zi[BCn*Rn*Mn];
__device__ float g_Or[BCn*Rn*Mn];       // mixed modes  [bc][r][k]
__device__ float g_Oi[BCn*Rn*Mn];
__device__ float g_Tr[BCn*Mn*Sn];       // inverse-H out [bc][k][h]
__device__ float g_Ti[BCn*Mn*Sn];
__device__ float g_cw[Mn*Sn];           // cos(2pi k w/256)
__device__ float g_sw[Mn*Sn];
__device__ float g_ch[Rn*Sn];           // cos(2pi ky h/256), ky in {0..11, 244..255}
__device__ float g_sh[Rn*Sn];

__global__ void k_setup() {
    int w = threadIdx.x;                 // 0..255
    const double c = 2.0 * M_PI / 256.0;
    for (int k = 0; k < Mn; k++) {
        int t = (k * w) & 255;
        double a = c * (double)t;
        g_cw[k*Sn + w] = (float)cos(a);
        g_sw[k*Sn + w] = (float)sin(a);
    }
    for (int r = 0; r < Rn; r++) {
        int ky = (r < Mn) ? r : (Sn - Mn + (r - Mn));
        int t = (ky * w) & 255;
        double a = c * (double)t;
        g_ch[r*Sn + w] = (float)cos(a);
        g_sh[r*Sn + w] = (float)sin(a);
    }
}

// lifting: h0[b,c,y,w] = pw[c,0]*x + pw[c,1]*gy + pw[c,2]*gx + pb[c]
__global__ void k_lift(const float* __restrict__ x,
                       const float* __restrict__ pw,
                       const float* __restrict__ pb) {
    int by = blockIdx.x;                 // b*S + y
    int b = by >> 8, y = by & 255;
    int w = threadIdx.x;
    float xin = x[(size_t)by*Sn + w];
    float gy = -1.f + (2.f/255.f) * (float)y;
    float gx = -1.f + (2.f/255.f) * (float)w;
    #pragma unroll 4
    for (int c = 0; c < Cn; c++) {
        float v = pw[c*3+0]*xin + pw[c*3+1]*gy + pw[c*3+2]*gx + pb[c];
        g_h0[(((size_t)(b*Cn + c))*Sn + y)*Sn + w] = v;
    }
}

// stage A: Y[bc,h,k] = sum_w h[bc,h,w] * e^{-2pi i k w/256}, k=0..11
// block: 128 thr, 16 rows; thread = (row, 3 consecutive q of 24 [12 re | 12 im])
__global__ void k_stageA(int sel) {
    const float* h = sel ? g_h1 : g_h0;
    int blk = blockIdx.x;
    int bc = blk >> 4;
    int rb = (blk & 15) * 16;
    __shared__ float4 s_x[16][65];       // padded: conflict-free across rows
    __shared__ float4 s_t[24][64];       // [q][w4], q<12: cos, q>=12: sin
    const float4* hrow = (const float4*)(h + ((size_t)bc*Sn + rb)*Sn);
    for (int i = threadIdx.x; i < 16*64; i += 128)
        s_x[i >> 6][i & 63] = hrow[i];
    for (int i = threadIdx.x; i < 24*64; i += 128) {
        int q = i >> 6, cc = i & 63;
        const float* tab = (q < Mn) ? (g_cw + q*Sn) : (g_sw + (q - Mn)*Sn);
        s_t[q][cc] = ((const float4*)tab)[cc];
    }
    __syncthreads();
    int row = threadIdx.x >> 3;
    int q0  = (threadIdx.x & 7) * 3;
    float a0 = 0.f, a1 = 0.f, a2 = 0.f;
    #pragma unroll 16
    for (int w4 = 0; w4 < 64; w4++) {
        float4 xv = s_x[row][w4];
        float4 t0 = s_t[q0+0][w4];
        float4 t1 = s_t[q0+1][w4];
        float4 t2 = s_t[q0+2][w4];
        a0 += xv.x*t0.x + xv.y*t0.y + xv.z*t0.z + xv.w*t0.w;
        a1 += xv.x*t1.x + xv.y*t1.y + xv.z*t1.z + xv.w*t1.w;
        a2 += xv.x*t2.x + xv.y*t2.y + xv.z*t2.z + xv.w*t2.w;
    }
    int hg = rb + row;
    size_t base = ((size_t)bc*Sn + hg)*Mn;
    float av[3] = {a0, a1, a2};
    #pragma unroll
    for (int j = 0; j < 3; j++) {
        int q = q0 + j;
        if (q < Mn) g_Yr[base + q]       =  av[j];
        else        g_Yi[base + q - Mn]  = -av[j];   // Yi = -sum x*sin
    }
}

// stage B: Z[bc,r,k] = sum_h Y[bc,h,k] * e^{-2pi i ky(r) h/256}
__global__ void k_stageB() {
    int bc = blockIdx.x;
    __shared__ float sYr[Sn*Mn];
    __shared__ float sYi[Sn*Mn];
    for (int i = threadIdx.x; i < Sn*Mn; i += 192) {
        sYr[i] = g_Yr[(size_t)bc*Sn*Mn + i];
        sYi[i] = g_Yi[(size_t)bc*Sn*Mn + i];
    }
    __syncthreads();
    int tid = threadIdx.x;               // 0..191
    int r = tid >> 3;                    // 0..23
    int m = tid & 7;
    int comp = m >> 2;                   // 0: real, 1: imag
    int k0 = (m & 3) * 3;                // 0,3,6,9
    float a0 = 0.f, a1 = 0.f, a2 = 0.f;
    const float* chp = g_ch + r*Sn;
    const float* shp = g_sh + r*Sn;
    for (int hh = 0; hh < Sn; hh++) {
        float cv = chp[hh], sv = shp[hh];
        int o = hh*Mn + k0;
        if (comp == 0) {
            a0 += sYr[o+0]*cv + sYi[o+0]*sv;
            a1 += sYr[o+1]*cv + sYi[o+1]*sv;
            a2 += sYr[o+2]*cv + sYi[o+2]*sv;
        } else {
            a0 += sYi[o+0]*cv - sYr[o+0]*sv;
            a1 += sYi[o+1]*cv - sYr[o+1]*sv;
            a2 += sYi[o+2]*cv - sYr[o+2]*sv;
        }
    }
    size_t ob = (size_t)bc*Rn*Mn + r*Mn + k0;
    if (comp == 0) { g_Zr[ob] = a0; g_Zr[ob+1] = a1; g_Zr[ob+2] = a2; }
    else           { g_Zi[ob] = a0; g_Zi[ob+1] = a1; g_Zi[ob+2] = a2; }
}

// mix: O[b,o,r,k] = (1/65536) * sum_i Z[b,i,r,k] * W[i,o,r',k]   (complex)
__global__ void k_mix(const float* __restrict__ w1r, const float* __restrict__ w1i,
                      const float* __restrict__ w2r, const float* __restrict__ w2i,
                      int l) {
    int rk = blockIdx.x;                 // 0..287
    int r = rk / Mn, k = rk % Mn;
    const float *Wr, *Wi; int kyw;
    if (r < Mn) { Wr = w1r; Wi = w1i; kyw = r; }
    else        { Wr = w2r; Wi = w2i; kyw = r - Mn; }
    size_t wbase = (size_t)l*Cn*Cn*Mn*Mn + (size_t)kyw*Mn + k;
    __shared__ float s_wr[Cn*Cn];
    __shared__ float s_wi[Cn*Cn];
    for (int idx = threadIdx.x; idx < Cn*Cn; idx += 256) {   // idx = i*32+o
        s_wr[idx] = Wr[wbase + (size_t)idx*(Mn*Mn)];
        s_wi[idx] = Wi[wbase + (size_t)idx*(Mn*Mn)];
    }
    __syncthreads();
    int warp = threadIdx.x >> 5, lane = threadIdx.x & 31;
    const float scale = 1.0f / (float)(Sn*Sn);
    for (int b = warp; b < Bn; b += 8) {
        size_t zidx = ((size_t)(b*Cn + lane))*Rn*Mn + rk;
        float zr = g_Zr[zidx], zi = g_Zi[zidx];
        float ar = 0.f, ai = 0.f;
        #pragma unroll
        for (int i = 0; i < Cn; i++) {
            float xr = __shfl_sync(0xffffffffu, zr, i);
            float xi = __shfl_sync(0xffffffffu, zi, i);
            float wr = s_wr[i*Cn + lane], wi = s_wi[i*Cn + lane];
            ar += xr*wr - xi*wi;
            ai += xr*wi + xi*wr;
        }
        g_Or[zidx] = ar*scale;
        g_Oi[zidx] = ai*scale;
    }
}

// inverse-H: T[bo,k,h] = sum_r O[bo,r,k] * e^{+2pi i ky(r) h/256}
__global__ void k_stageBinv() {
    int bo = blockIdx.x;
    __shared__ float sOr[Rn*Mn];
    __shared__ float sOi[Rn*Mn];
    for (int i = threadIdx.x; i < Rn*Mn; i += 256) {
        sOr[i] = g_Or[(size_t)bo*Rn*Mn + i];
        sOi[i] = g_Oi[(size_t)bo*Rn*Mn + i];
    }
    __syncthreads();
    int hh = threadIdx.x;
    float cv[Rn], sv[Rn];
    #pragma unroll
    for (int r = 0; r < Rn; r++) { cv[r] = g_ch[r*Sn + hh]; sv[r] = g_sh[r*Sn + hh]; }
    #pragma unroll 4
    for (int k = 0; k < Mn; k++) {
        float tr = 0.f, ti = 0.f;
        #pragma unroll
        for (int r = 0; r < Rn; r++) {
            float Or = sOr[r*Mn + k], Oi = sOi[r*Mn + k];
            tr += Or*cv[r] - Oi*sv[r];
            ti += Or*sv[r] + Oi*cv[r];
        }
        size_t tb = ((size_t)bo*Mn + k)*Sn + hh;
        g_Tr[tb] = tr;
        g_Ti[tb] = ti;
    }
}

// fused: inverse-W reconstruction + pointwise conv + bias (+ReLU | +projection)
__global__ void k_final(int sel,
                        const float* __restrict__ wsw, const float* __restrict__ wsb,
                        const float* __restrict__ qw,  const float* __restrict__ qb,
                        int l, int do_relu, int do_proj, float* __restrict__ out) {
    const float* hc = sel ? g_h1 : g_h0;
    float* hn       = sel ? g_h0 : g_h1;
    int by = blockIdx.x;
    int b = by >> 8, y = by & 255;
    __shared__ float s_tr[Cn*Mn];
    __shared__ float s_ti[Cn*Mn];
    __shared__ float s_ws[Cn*Cn];
    __shared__ float s_wb[Cn];
    __shared__ float s_qw[Cn];
    for (int idx = threadIdx.x; idx < Cn*Mn; idx += 256) {
        int o = idx / Mn, k = idx % Mn;
        size_t tb = (((size_t)(b*Cn + o))*Mn + k)*Sn + y;
        s_tr[idx] = g_Tr[tb];
        s_ti[idx] = g_Ti[tb];
    }
    for (int idx = threadIdx.x; idx < Cn*Cn; idx += 256)
        s_ws[idx] = wsw[(size_t)l*Cn*Cn + idx];          // [o][i]
    if (threadIdx.x < Cn) {
        s_wb[threadIdx.x] = wsb[l*Cn + threadIdx.x];
        s_qw[threadIdx.x] = qw[threadIdx.x];
    }
    __syncthreads();
    int w = threadIdx.x;
    float cww[Mn], sww[Mn];
    #pragma unroll
    for (int k = 0; k < Mn; k++) { cww[k] = g_cw[k*Sn + w]; sww[k] = g_sw[k*Sn + w]; }
    float hin[Cn];
    size_t hbase = (((size_t)b*Cn)*Sn + y)*Sn + w;
    #pragma unroll
    for (int i = 0; i < Cn; i++) hin[i] = hc[hbase + (size_t)i*Sn*Sn];
    float proj = 0.f;
    #pragma unroll 4
    for (int o = 0; o < Cn; o++) {
        float acc = s_wb[o];
        #pragma unroll
        for (int i = 0; i < Cn; i++) acc += s_ws[o*Cn + i]*hin[i];
        float four = s_tr[o*Mn];                          // DC: imag ignored (C2R)
        #pragma unroll
        for (int k = 1; k < Mn; k++)
            four += 2.f*(s_tr[o*Mn + k]*cww[k] - s_ti[o*Mn + k]*sww[k]);
        float v = acc + four;
        if (do_relu) v = fmaxf(v, 0.f);
        if (do_proj) proj += s_qw[o]*v;
        else         hn[hbase + (size_t)o*Sn*Sn] = v;
    }
    if (do_proj) out[(size_t)by*Sn + w] = proj + qb[0];
}

extern "C" void kernel_launch(void* const* d_in, const int* in_sizes, int n_in,
                              void* d_out, int out_size) {
    (void)in_sizes; (void)n_in; (void)out_size;
    const float* x    = (const float*)d_in[0];
    const float* p_w  = (const float*)d_in[1];
    const float* p_b  = (const float*)d_in[2];
    const float* ws_w = (const float*)d_in[3];
    const float* ws_b = (const float*)d_in[4];
    const float* w1r  = (const float*)d_in[5];
    const float* w1i  = (const float*)d_in[6];
    const float* w2r  = (const float*)d_in[7];
    const float* w2i  = (const float*)d_in[8];
    const float* q_w  = (const float*)d_in[9];
    const float* q_b  = (const float*)d_in[10];
    float* out = (float*)d_out;

    k_setup<<<1, 256>>>();
    k_lift<<<Bn*Sn, 256>>>(x, p_w, p_b);
    int sel = 0;
    for (int l = 0; l < Ln; l++) {
        k_stageA  <<<BCn*16, 128>>>(sel);
        k_stageB  <<<BCn,    192>>>();
        k_mix     <<<Rn*Mn,  256>>>(w1r, w1i, w2r, w2i, l);
        k_stageBinv<<<BCn,   256>>>();
        k_final   <<<Bn*Sn,  256>>>(sel, ws_w, ws_b, q_w, q_b,
                                    l, (l < Ln-1) ? 1 : 0, (l == Ln-1) ? 1 : 0, out);
        sel ^= 1;
    }
}

// round 3
// speedup vs baseline: 2.8931x; 2.8844x over previous
#include <cuda_runtime.h>

#define Bn 16
#define Cn 32
#define Sn 256
#define Mn 12
#define Rn 24
#define Ln 4
#define BCn (Bn*Cn)
#define WTN (Ln*Rn*Mn*Cn*Cn)   // 1,179,648

// ---- scratch (device globals: no allocation allowed) ----
__device__ float g_h[(size_t)BCn*Sn*Sn];           // 134 MB, updated in place
__device__ float g_Y[(size_t)BCn*Sn*(2*Mn)];       // [bc][h][q] q<12: re, q>=12: im
__device__ float g_T[(size_t)Bn*Sn*Cn*(2*Mn)];     // [b][y][o][q] q<12: re, q>=12: im
__device__ float g_Wtr[WTN];                       // [l][r][k][i][o], scaled
__device__ float g_Wti[WTN];
__device__ float g_trig[Rn*Sn];                    // rows 0-11 cos(2pi k w/256), 12-23 sin
__device__ float g_ch[Rn*Sn];                      // cos(2pi ky h/256), ky in {0..11,244..255}
__device__ float g_sh[Rn*Sn];

__global__ void k_setup() {
    int q = blockIdx.x, w = threadIdx.x;
    float s, c;
    int kq = (q < Mn) ? q : q - Mn;
    sincospif((float)((kq*w) & 255) * (2.0f/256.0f), &s, &c);
    g_trig[q*Sn + w] = (q < Mn) ? c : s;
    int ky = (q < Mn) ? q : 232 + q;     // 244..255 for q=12..23
    sincospif((float)((ky*w) & 255) * (2.0f/256.0f), &s, &c);
    g_ch[q*Sn + w] = c;
    g_sh[q*Sn + w] = s;
}

// transpose spectral weights to [l][r][k][i][o] and fold 1/65536
__global__ void k_wt(const float* __restrict__ w1r, const float* __restrict__ w1i,
                     const float* __restrict__ w2r, const float* __restrict__ w2i) {
    int flat = blockIdx.x*256 + threadIdx.x;
    if (flat >= WTN) return;
    int o = flat & 31;
    int i = (flat >> 5) & 31;
    int k = (flat >> 10) % Mn;
    int r = (flat / (Mn*Cn*Cn)) % Rn;
    int l =  flat / (Rn*Mn*Cn*Cn);
    int ky = (r < Mn) ? r : r - Mn;
    size_t s = ((((size_t)l*Cn + i)*Cn + o)*Mn + ky)*Mn + k;
    const float sc = 1.0f/65536.0f;
    if (r < Mn) { g_Wtr[flat] = w1r[s]*sc; g_Wti[flat] = w1i[s]*sc; }
    else        { g_Wtr[flat] = w2r[s]*sc; g_Wti[flat] = w2i[s]*sc; }
}

// fused: stageB (DFT over h) + channel mix + inverse-H.  block = (b, k), 24 warps.
__global__ void __launch_bounds__(768) k_modes(int l) {
    extern __shared__ float sm[];
    float* sYr = sm;                       // [32][257]
    float* sYi = sm + Cn*257;
    float* sZr = sm + 2*Cn*257;            // [32][25]
    float* sZi = sZr + Cn*25;
    float* sOr = sZi + Cn*25;              // [32][25]
    float* sOi = sOr + Cn*25;
    int b = blockIdx.x / Mn, k = blockIdx.x % Mn;
    int t = threadIdx.x;

    for (int idx = t; idx < Cn*Sn; idx += 768) {
        int c = idx >> 8, h = idx & 255;
        const float* yp = g_Y + ((size_t)(b*Cn + c)*Sn + h)*(2*Mn);
        sYr[c*257 + h] = yp[k];
        sYi[c*257 + h] = yp[Mn + k];
    }
    __syncthreads();

    int warp = t >> 5, lane = t & 31;
    {   // stage B: Z[c,r] = sum_h Y[c,h] e^{-2pi i ky(r) h/256}; warp=r, lane=c
        int r = warp;
        const float* chp = g_ch + r*Sn;
        const float* shp = g_sh + r*Sn;
        const float* yr = sYr + lane*257;
        const float* yi = sYi + lane*257;
        float zr = 0.f, zi = 0.f;
        #pragma unroll 8
        for (int h = 0; h < Sn; h++) {
            float cv = __ldg(chp + h), sv = __ldg(shp + h);
            float a = yr[h], bb = yi[h];
            zr += a*cv + bb*sv;
            zi += bb*cv - a*sv;
        }
        sZr[lane*25 + r] = zr;
        sZi[lane*25 + r] = zi;
    }
    __syncthreads();
    {   // mix: O[o,r] = sum_i Z[i,r] * W[i,o]  (complex, scale prefolded); warp=r, lane=o
        int r = warp;
        size_t wb = ((size_t)((l*Rn + r)*Mn + k))*(Cn*Cn) + lane;
        const float* wr = g_Wtr + wb;
        const float* wi = g_Wti + wb;
        float orr = 0.f, oii = 0.f;
        #pragma unroll 8
        for (int i = 0; i < Cn; i++) {
            float zr = sZr[i*25 + r], zi = sZi[i*25 + r];
            float ar = wr[(size_t)i*Cn], ai = wi[(size_t)i*Cn];
            orr += zr*ar - zi*ai;
            oii += zr*ai + zi*ar;
        }
        sOr[lane*25 + r] = orr;
        sOi[lane*25 + r] = oii;
    }
    __syncthreads();
    if (t < Sn) {   // inverse H: T[o,h] = sum_r O[o,r] e^{+2pi i ky(r) h/256}; thread=h
        int h = t;
        float cv[Rn], sv[Rn];
        #pragma unroll
        for (int r = 0; r < Rn; r++) { cv[r] = g_ch[r*Sn + h]; sv[r] = g_sh[r*Sn + h]; }
        float* tb = g_T + ((size_t)(b*Sn + h))*Cn*(2*Mn);
        for (int o = 0; o < Cn; o++) {
            float tr = 0.f, ti = 0.f;
            #pragma unroll
            for (int r = 0; r < Rn; r++) {
                float Or = sOr[o*25 + r], Oi = sOi[o*25 + r];
                tr += Or*cv[r] - Oi*sv[r];
                ti += Or*sv[r] + Oi*cv[r];
            }
            tb[o*(2*Mn) + k]      = tr;
            tb[o*(2*Mn) + Mn + k] = ti;
        }
    }
}

// fused per-row kernel. MODE 0: lift + row-DFT. MODE 1: inverse-W + conv + ReLU,
// write h in place, row-DFT for next layer. MODE 2: inverse-W + conv + projection.
template<int MODE>
__global__ void __launch_bounds__(256) k_layer(
    const float* __restrict__ x,
    const float* __restrict__ pw, const float* __restrict__ pb,
    const float* __restrict__ wsw, const float* __restrict__ wsb,
    const float* __restrict__ qw, const float* __restrict__ qb,
    int l, float* __restrict__ out)
{
    extern __shared__ float sm[];
    float* s_v    = sm;                      // [32][260]
    float* s_trig = sm + Cn*260;             // [24][260]
    float* s_t12  = sm + (Cn + Rn)*260;      // [32][24]
    float* s_ws   = s_t12 + Cn*(2*Mn);       // [32][32]
    float* s_wb   = s_ws + Cn*Cn;
    float* s_qw   = s_wb + Cn;

    int t = threadIdx.x;
    int b = blockIdx.x >> 8, y = blockIdx.x & 255;

    for (int i = t; i < Rn*Sn; i += 256)
        s_trig[(i >> 8)*260 + (i & 255)] = g_trig[i];
    if (MODE >= 1) {
        const float* tbp = g_T + (size_t)blockIdx.x * (Cn*2*Mn);
        for (int i = t; i < Cn*2*Mn; i += 256) s_t12[i] = tbp[i];
        for (int i = t; i < Cn*Cn; i += 256)   s_ws[i] = wsw[l*Cn*Cn + i];
        if (t < Cn) { s_wb[t] = wsb[l*Cn + t]; s_qw[t] = qw[t]; }
    }
    __syncthreads();

    int w = t;
    float* hrow = g_h + (((size_t)b*Cn)*Sn + y)*Sn + w;   // + c*Sn*Sn per channel

    if (MODE == 0) {
        float xin = x[(size_t)blockIdx.x*Sn + w];
        float gy = -1.f + (2.f/255.f)*(float)y;
        float gx = -1.f + (2.f/255.f)*(float)w;
        #pragma unroll 8
        for (int c = 0; c < Cn; c++) {
            float v = pw[c*3+0]*xin + pw[c*3+1]*gy + pw[c*3+2]*gx + pb[c];
            hrow[(size_t)c*(Sn*Sn)] = v;
            s_v[c*260 + w] = v;
        }
    } else {
        float cww[Mn], sww[Mn];
        #pragma unroll
        for (int k = 0; k < Mn; k++) {
            cww[k] = s_trig[k*260 + w];
            sww[k] = s_trig[(Mn + k)*260 + w];
        }
        float hin[Cn];
        #pragma unroll
        for (int i = 0; i < Cn; i++) hin[i] = hrow[(size_t)i*(Sn*Sn)];
        float proj = 0.f;
        #pragma unroll 2
        for (int o = 0; o < Cn; o++) {
            const float* wsp = s_ws + o*Cn;
            float acc = s_wb[o];
            #pragma unroll
            for (int i = 0; i < Cn; i++) acc += wsp[i]*hin[i];
            const float* tp = s_t12 + o*(2*Mn);
            float four = tp[0];                       // DC: imag ignored (C2R)
            #pragma unroll
            for (int k = 1; k < Mn; k++)
                four += 2.f*(tp[k]*cww[k] - tp[Mn+k]*sww[k]);
            float v = acc + four;
            if (MODE == 1) {
                v = fmaxf(v, 0.f);
                hrow[(size_t)o*(Sn*Sn)] = v;          // in place: hin already read
                s_v[o*260 + w] = v;
            } else {
                proj += s_qw[o]*v;
            }
        }
        if (MODE == 2) {
            out[(size_t)blockIdx.x*Sn + w] = proj + qb[0];
            return;
        }
    }
    __syncthreads();

    // row DFT: Y[q] = sum_w v(w) trig[q][w]; thread = (o = t>>3, q0 = (t&7)*3)
    int o = t >> 3, q0 = (t & 7)*3;
    const float4* xv4 = (const float4*)(s_v + o*260);
    const float4* t0p = (const float4*)(s_trig + q0*260);
    const float4* t1p = (const float4*)(s_trig + (q0+1)*260);
    const float4* t2p = (const float4*)(s_trig + (q0+2)*260);
    float a0 = 0.f, a1 = 0.f, a2 = 0.f;
    #pragma unroll 8
    for (int w4 = 0; w4 < 64; w4++) {
        float4 xv = xv4[w4];
        float4 u0 = t0p[w4], u1 = t1p[w4], u2 = t2p[w4];
        a0 += xv.x*u0.x + xv.y*u0.y + xv.z*u0.z + xv.w*u0.w;
        a1 += xv.x*u1.x + xv.y*u1.y + xv.z*u1.z + xv.w*u1.w;
        a2 += xv.x*u2.x + xv.y*u2.y + xv.z*u2.z + xv.w*u2.w;
    }
    float sg = (q0 >= Mn) ? -1.f : 1.f;              // Yi = -sum v*sin
    float* yb = g_Y + ((size_t)(b*Cn + o)*Sn + y)*(2*Mn) + q0;
    yb[0] = sg*a0; yb[1] = sg*a1; yb[2] = sg*a2;
}

#define SMEM_LAYER ((Cn*260 + Rn*260 + Cn*2*Mn + Cn*Cn + 2*Cn)*4)
#define SMEM_MODES ((2*Cn*257 + 4*Cn*25)*4)

extern "C" void kernel_launch(void* const* d_in, const int* in_sizes, int n_in,
                              void* d_out, int out_size) {
    (void)in_sizes; (void)n_in; (void)out_size;
    const float* x    = (const float*)d_in[0];
    const float* p_w  = (const float*)d_in[1];
    const float* p_b  = (const float*)d_in[2];
    const float* ws_w = (const float*)d_in[3];
    const float* ws_b = (const float*)d_in[4];
    const float* w1r  = (const float*)d_in[5];
    const float* w1i  = (const float*)d_in[6];
    const float* w2r  = (const float*)d_in[7];
    const float* w2i  = (const float*)d_in[8];
    const float* q_w  = (const float*)d_in[9];
    const float* q_b  = (const float*)d_in[10];
    float* out = (float*)d_out;

    cudaFuncSetAttribute(k_layer<0>, cudaFuncAttributeMaxDynamicSharedMemorySize, SMEM_LAYER);
    cudaFuncSetAttribute(k_layer<1>, cudaFuncAttributeMaxDynamicSharedMemorySize, SMEM_LAYER);
    cudaFuncSetAttribute(k_layer<2>, cudaFuncAttributeMaxDynamicSharedMemorySize, SMEM_LAYER);
    cudaFuncSetAttribute(k_modes,    cudaFuncAttributeMaxDynamicSharedMemorySize, SMEM_MODES);

    k_setup<<<Rn, Sn>>>();
    k_wt<<<(WTN + 255)/256, 256>>>(w1r, w1i, w2r, w2i);
    k_layer<0><<<Bn*Sn, 256, SMEM_LAYER>>>(x, p_w, p_b, nullptr, nullptr, nullptr, nullptr, 0, out);
    for (int l = 0; l < Ln; l++) {
        k_modes<<<Bn*Mn, 768, SMEM_MODES>>>(l);
        if (l < Ln - 1)
            k_layer<1><<<Bn*Sn, 256, SMEM_LAYER>>>(nullptr, nullptr, nullptr,
                                                   ws_w, ws_b, q_w, q_b, l, out);
        else
            k_layer<2><<<Bn*Sn, 256, SMEM_LAYER>>>(nullptr, nullptr, nullptr,
                                                   ws_w, ws_b, q_w, q_b, l, out);
    }
}